// round 15
// baseline (speedup 1.0000x reference)
#include <cuda_runtime.h>
#include <cuda_fp16.h>
#include <cstdint>

// ---------------------------------------------------------------------------
// Problem constants
// ---------------------------------------------------------------------------
#define B_   65536
#define N_   2
#define D_   512
#define T_   (B_ * N_)          // 131072 tokens
#define TD_  ((size_t)T_ * D_)  // 67,108,864

// ---------------------------------------------------------------------------
// Scratch (static __device__ arrays)
// ---------------------------------------------------------------------------
__device__ float  g_sp[(size_t)T_ * 16];  // score partials
__device__ float  g_buv[1024];     // bias for uv GEMM: w_b | bvo
__device__ float  g_wa[512], g_gamma[1];

__device__ __half g_xh[TD_];
__device__ __half g_hh[TD_];       // h fp16 (residual + FFN input)
__device__ __half g_rh[TD_];
__device__ __half g_ph[TD_];       // v' buffer, later (h + FFN) fp16 sum
__device__ __half g_fh[2 * TD_];
__device__ __half g_wq16[262144], g_wk16[262144], g_wv16[262144]; // row-major fp16

// transposed fp16 weights, [N,K] layout
#define WK_OFF  262144   // Mt lives here; contiguous with WVO for fused uv GEMM
#define WVO_OFF 524288   // Wvo_t lives here
#define WO_OFF  786432   // wo_t (used only to build Wvo_t)
#define WF1_OFF 1048576
#define WF2_OFF 1572864
#define WS1_OFF 2097152
__device__ __half g_wt[2359296];

// ---------------------------------------------------------------------------
// PTX helpers (baseline sm_80+)
// ---------------------------------------------------------------------------
__device__ __forceinline__ uint32_t smem_u32(const void* smem_ptr) {
    uint32_t addr;
    asm("{ .reg .u64 tmp; cvta.to.shared.u64 tmp, %1; cvt.u32.u64 %0, tmp; }"
        : "=r"(addr) : "l"(smem_ptr));
    return addr;
}

#define CP16(dst, src) \
    asm volatile("cp.async.cg.shared.global [%0], [%1], 16;" \
        :: "r"(dst), "l"(src))

#define CP_COMMIT() asm volatile("cp.async.commit_group;" ::: "memory")
#define CP_WAIT(n)  asm volatile("cp.async.wait_group %0;" :: "n"(n) : "memory")

#define LDSM4(r0, r1, r2, r3, a) \
    asm volatile("ldmatrix.sync.aligned.m8n8.x4.shared.b16 {%0,%1,%2,%3}, [%4];" \
        : "=r"(r0), "=r"(r1), "=r"(r2), "=r"(r3) : "r"(a))

#define MMAH(d, a0, a1, a2, a3, b0, b1) \
    asm volatile("mma.sync.aligned.m16n8k16.row.col.f32.f16.f16.f32 " \
        "{%0,%1,%2,%3}, {%4,%5,%6,%7}, {%8,%9}, {%0,%1,%2,%3};" \
        : "+f"((d)[0]), "+f"((d)[1]), "+f"((d)[2]), "+f"((d)[3]) \
        : "r"(a0), "r"(a1), "r"(a2), "r"(a3), "r"(b0), "r"(b1))

__device__ __forceinline__ float warp_sum(float v) {
#pragma unroll
    for (int o = 16; o; o >>= 1) v += __shfl_xor_sync(0xffffffffu, v, o);
    return v;
}

// dot of 8 fp16 (uint4) with 8 fp32 (two float4)
__device__ __forceinline__ float dot8f(uint4 a, float4 w0, float4 w1) {
    const __half2* pa = (const __half2*)&a;
    float2 f0 = __half22float2(pa[0]);
    float2 f1 = __half22float2(pa[1]);
    float2 f2 = __half22float2(pa[2]);
    float2 f3 = __half22float2(pa[3]);
    return f0.x * w0.x + f0.y * w0.y + f1.x * w0.z + f1.y * w0.w +
           f2.x * w1.x + f2.y * w1.y + f3.x * w1.z + f3.y * w1.w;
}

// ---------------------------------------------------------------------------
// mma.sync GEMM: CTA 128x128, 8 warps, K-chunk 64, 3-stage cp.async,
// 2 CTAs/SM, stride-144B smem rows.
// mode: 0 fp32; 1 fp32+ReLU; 2 fp16+ReLU; 3 fp16;
//       4 score-fused: relu(v+bias) dot ws2 -> partials Cf[row*8 + bn*2 + wn]
//       5 uv-fused: bn<4 -> u'.x_m partials; bn>=4 -> v' fp16 [T,512]
//       6 residual-fused: fp16( acc + bias + resid[r,c] ) where resid = C2
// Dual-problem: if A2 != nullptr and bm >= bsplit -> (A2, B2, C2).
// ---------------------------------------------------------------------------
#define STAGES        3
#define ROW_STRIDE    144
#define MAT_BYTES     18432
#define STAGE_BYTES   36864
#define GEMM_SMEM     (STAGES * STAGE_BYTES)   // 110592

__global__ __launch_bounds__(256, 2)
void gemm_mma(const __half* __restrict__ A, const __half* __restrict__ B,
              const float* __restrict__ bias,
              float* __restrict__ Cf, __half* __restrict__ Ch,
              int N, int K, int mode, const float* __restrict__ ws2,
              const __half* A2, const __half* B2, __half* C2, int bsplit)
{
    extern __shared__ char smem[];
    const uint32_t sb = smem_u32(smem);
    const int tid  = threadIdx.x;
    const int lane = tid & 31;
    const int wid  = tid >> 5;
    const int wm   = wid & 3;
    const int wn   = wid >> 2;
    const int bn   = blockIdx.x;
    int bm         = blockIdx.y;
    const int Kb   = K * 2;

    const __half* Ap = A;
    const __half* Bp = B;
    __half*       Chp = Ch;
    if (A2 != nullptr && bm >= bsplit) {
        bm -= bsplit;
        Ap = A2; Bp = B2; Chp = C2;
    }

    const char* gA = (const char*)(Ap + (size_t)bm * 128 * K);
    const char* gB = (const char*)(Bp + (size_t)bn * 128 * K);

    const int lr  = tid >> 1;
    const int lcb = (tid & 1) * 64;
    const size_t   goff = (size_t)lr * Kb + lcb;
    const uint32_t soff = (uint32_t)lr * ROW_STRIDE + lcb;

    float acc[2][8][4];
#pragma unroll
    for (int mi = 0; mi < 2; mi++)
#pragma unroll
        for (int ni = 0; ni < 8; ni++)
#pragma unroll
            for (int r = 0; r < 4; r++) acc[mi][ni][r] = 0.0f;

    const int nch = K >> 6;

#define LOAD_STAGE(stage, kc) do {                                        \
        uint32_t d = sb + (uint32_t)(stage) * STAGE_BYTES + soff;         \
        size_t   g = goff + (size_t)(kc) * 128;                           \
        CP16(d,                   gA + g);                                \
        CP16(d + 16,              gA + g + 16);                           \
        CP16(d + 32,              gA + g + 32);                           \
        CP16(d + 48,              gA + g + 48);                           \
        CP16(d + MAT_BYTES,       gB + g);                                \
        CP16(d + MAT_BYTES + 16,  gB + g + 16);                           \
        CP16(d + MAT_BYTES + 32,  gB + g + 32);                           \
        CP16(d + MAT_BYTES + 48,  gB + g + 48);                           \
    } while (0)

#pragma unroll
    for (int s = 0; s < STAGES - 1; s++) { LOAD_STAGE(s, s); CP_COMMIT(); }

    const uint32_t a_row  = (uint32_t)(wm * 32 + (lane & 15));
    const uint32_t a_coff = (uint32_t)((lane >> 4) * 16);
    const uint32_t b_row  = (uint32_t)(wn * 64 + ((lane >> 4) * 8) + (lane & 7));
    const uint32_t b_coff = (uint32_t)(((lane >> 3) & 1) * 16);

    int cur = 0;
    int ld  = STAGES - 1;

#pragma unroll 1
    for (int i = 0; i < nch; i++) {
        CP_WAIT(STAGES - 2);
        __syncthreads();

        int nxt = i + STAGES - 1;
        if (nxt < nch) LOAD_STAGE(ld, nxt);
        CP_COMMIT();

        const uint32_t base = sb + (uint32_t)cur * STAGE_BYTES;

#pragma unroll
        for (int kk = 0; kk < 4; kk++) {
            const uint32_t kb = kk * 32;
            uint32_t ar[2][4], br[8][2];
#pragma unroll
            for (int mi = 0; mi < 2; mi++) {
                uint32_t ad = base + (a_row + mi * 16) * ROW_STRIDE + kb + a_coff;
                LDSM4(ar[mi][0], ar[mi][1], ar[mi][2], ar[mi][3], ad);
            }
#pragma unroll
            for (int p = 0; p < 4; p++) {
                uint32_t bd = base + MAT_BYTES +
                              (b_row + p * 16) * ROW_STRIDE + kb + b_coff;
                uint32_t r0, r1, r2, r3;
                LDSM4(r0, r1, r2, r3, bd);
                br[2*p][0] = r0;   br[2*p][1] = r1;
                br[2*p+1][0] = r2; br[2*p+1][1] = r3;
            }
#pragma unroll
            for (int mi = 0; mi < 2; mi++)
#pragma unroll
                for (int ni = 0; ni < 8; ni++)
                    MMAH(acc[mi][ni], ar[mi][0], ar[mi][1], ar[mi][2], ar[mi][3],
                         br[ni][0], br[ni][1]);
        }
        cur = (cur + 1 == STAGES) ? 0 : cur + 1;
        ld  = (ld  + 1 == STAGES) ? 0 : ld  + 1;
    }
#undef LOAD_STAGE

    // epilogue
    const int row0 = bm * 128 + wm * 32 + (lane >> 2);
    const int col0 = bn * 128 + wn * 64 + (lane & 3) * 2;

    if (mode == 5 && bn < 4) {
#pragma unroll
        for (int mi = 0; mi < 2; mi++) {
            const int r  = row0 + mi * 16;
            const int r2 = r + 8;
            const __half* xs0 = Ap + (size_t)(r  & ~1) * 512;
            const __half* xs2 = Ap + (size_t)(r2 & ~1) * 512;
            float pa00 = 0.f, pa01 = 0.f, pa10 = 0.f, pa11 = 0.f;
#pragma unroll
            for (int ni = 0; ni < 8; ni++) {
                const int c = col0 + ni * 8;
                const float b0 = __ldg(bias + c);
                const float b1 = __ldg(bias + c + 1);
                float u00 = acc[mi][ni][0] + b0;
                float u01 = acc[mi][ni][1] + b1;
                float u10 = acc[mi][ni][2] + b0;
                float u11 = acc[mi][ni][3] + b1;
                float2 fa = __half22float2(*(const __half2*)(xs0 + c));
                float2 fb = __half22float2(*(const __half2*)(xs0 + 512 + c));
                float2 fc = __half22float2(*(const __half2*)(xs2 + c));
                float2 fd = __half22float2(*(const __half2*)(xs2 + 512 + c));
                pa00 += u00 * fa.x + u01 * fa.y;
                pa01 += u00 * fb.x + u01 * fb.y;
                pa10 += u10 * fc.x + u11 * fc.y;
                pa11 += u10 * fd.x + u11 * fd.y;
            }
            pa00 += __shfl_xor_sync(0xffffffffu, pa00, 1);
            pa00 += __shfl_xor_sync(0xffffffffu, pa00, 2);
            pa01 += __shfl_xor_sync(0xffffffffu, pa01, 1);
            pa01 += __shfl_xor_sync(0xffffffffu, pa01, 2);
            pa10 += __shfl_xor_sync(0xffffffffu, pa10, 1);
            pa10 += __shfl_xor_sync(0xffffffffu, pa10, 2);
            pa11 += __shfl_xor_sync(0xffffffffu, pa11, 1);
            pa11 += __shfl_xor_sync(0xffffffffu, pa11, 2);
            if ((lane & 3) == 0) {
                Cf[(size_t)r  * 16 + 0 + bn * 2 + wn] = pa00;
                Cf[(size_t)r  * 16 + 8 + bn * 2 + wn] = pa01;
                Cf[(size_t)r2 * 16 + 0 + bn * 2 + wn] = pa10;
                Cf[(size_t)r2 * 16 + 8 + bn * 2 + wn] = pa11;
            }
        }
        return;
    }

#pragma unroll
    for (int mi = 0; mi < 2; mi++) {
        float s0 = 0.f, s1 = 0.f;
#pragma unroll
        for (int ni = 0; ni < 8; ni++) {
            const int r = row0 + mi * 16;
            const int c = col0 + ni * 8;
            const float b0 = __ldg(bias + c);
            const float b1 = __ldg(bias + c + 1);
            float v00 = acc[mi][ni][0] + b0;
            float v01 = acc[mi][ni][1] + b1;
            float v10 = acc[mi][ni][2] + b0;
            float v11 = acc[mi][ni][3] + b1;
            if (mode == 1 || mode == 2 || mode == 4) {
                v00 = fmaxf(v00, 0.0f); v01 = fmaxf(v01, 0.0f);
                v10 = fmaxf(v10, 0.0f); v11 = fmaxf(v11, 0.0f);
            }
            if (mode == 4) {
                const float w0 = __ldg(ws2 + c);
                const float w1 = __ldg(ws2 + c + 1);
                s0 += v00 * w0 + v01 * w1;
                s1 += v10 * w0 + v11 * w1;
            } else if (mode == 5) {
                __half2 h0 = __floats2half2_rn(v00, v01);
                __half2 h1 = __floats2half2_rn(v10, v11);
                *(__half2*)(Chp + (size_t)r * 512 + (c - 512))       = h0;
                *(__half2*)(Chp + (size_t)(r + 8) * 512 + (c - 512)) = h1;
            } else if (mode == 6) {
                // residual add from C2 (fp16), write fp16 sum
                float2 ra = __half22float2(*(const __half2*)(C2 + (size_t)r * N + c));
                float2 rb = __half22float2(*(const __half2*)(C2 + (size_t)(r + 8) * N + c));
                __half2 h0 = __floats2half2_rn(v00 + ra.x, v01 + ra.y);
                __half2 h1 = __floats2half2_rn(v10 + rb.x, v11 + rb.y);
                *(__half2*)(Chp + (size_t)r * N + c)       = h0;
                *(__half2*)(Chp + (size_t)(r + 8) * N + c) = h1;
            } else if (mode >= 2) {
                __half2 h0 = __floats2half2_rn(v00, v01);
                __half2 h1 = __floats2half2_rn(v10, v11);
                *(__half2*)(Chp + (size_t)r * N + c)       = h0;
                *(__half2*)(Chp + (size_t)(r + 8) * N + c) = h1;
            } else {
                *(float2*)(Cf + (size_t)r * N + c)       = make_float2(v00, v01);
                *(float2*)(Cf + (size_t)(r + 8) * N + c) = make_float2(v10, v11);
            }
        }
        if (mode == 4) {
            s0 += __shfl_xor_sync(0xffffffffu, s0, 1);
            s0 += __shfl_xor_sync(0xffffffffu, s0, 2);
            s1 += __shfl_xor_sync(0xffffffffu, s1, 1);
            s1 += __shfl_xor_sync(0xffffffffu, s1, 2);
            if ((lane & 3) == 0) {
                const int r = row0 + mi * 16;
                Cf[(size_t)r * 8 + bn * 2 + wn]       = s0;
                Cf[(size_t)(r + 8) * 8 + bn * 2 + wn] = s1;
            }
        }
    }
}

// ---------------------------------------------------------------------------
// Mega-prep kernel (unchanged from R14)
// ---------------------------------------------------------------------------
#define NBX 65536
#define NBW 6912
#define NBB 2
#define PREP_BLOCKS (NBX + NBW + NBB)

__global__ __launch_bounds__(256)
void prep_all(const float* __restrict__ x,
              const float* __restrict__ wq, const float* __restrict__ wk,
              const float* __restrict__ wv, const float* __restrict__ wo,
              const float* __restrict__ wf1, const float* __restrict__ wf2,
              const float* __restrict__ ws1,
              const float* __restrict__ bq, const float* __restrict__ bk,
              const float* __restrict__ bv, const float* __restrict__ bo,
              __half* __restrict__ xh,
              __half* __restrict__ wq16, __half* __restrict__ wk16,
              __half* __restrict__ wv16, __half* __restrict__ wt,
              float* __restrict__ w_a,
              float* __restrict__ gamma, float* __restrict__ buv)
{
    int bid = blockIdx.x;
    int tid = threadIdx.x;

    if (bid < NBX) {
        size_t i = (size_t)bid * 256 + tid;
        float4 v = ((const float4*)x)[i];
        __half2 h0 = __floats2half2_rn(v.x, v.y);
        __half2 h1 = __floats2half2_rn(v.z, v.w);
        uint2 o;
        o.x = *(uint32_t*)&h0;
        o.y = *(uint32_t*)&h1;
        ((uint2*)xh)[i] = o;
        return;
    }
    if (bid < NBX + NBW) {
        int idx = (bid - NBX) * 256 + tid;
        if (idx < 196608) {
            int sec = idx >> 16;
            int i4  = idx & 65535;
            const float* src = sec == 0 ? wq : (sec == 1 ? wk : wv);
            __half* dst      = sec == 0 ? wq16 : (sec == 1 ? wk16 : wv16);
            float4 v = ((const float4*)src)[i4];
            __half2 h0 = __floats2half2_rn(v.x, v.y);
            __half2 h1 = __floats2half2_rn(v.z, v.w);
            uint2 o;
            o.x = *(uint32_t*)&h0;
            o.y = *(uint32_t*)&h1;
            ((uint2*)dst)[i4] = o;
            return;
        }
        int t = idx - 196608;
        if (t < 262144) {
            int n = t >> 9, k = t & 511;
            wt[WO_OFF + t] = __float2half_rn(wo[(size_t)k * 512 + n]);
            return;
        }
        t -= 262144;
        if (t < 524288) {
            int n = t >> 9, k = t & 511;
            wt[WF1_OFF + t] = __float2half_rn(wf1[(size_t)k * 1024 + n]);
            return;
        }
        t -= 524288;
        if (t < 524288) {
            int n = t >> 10, k = t & 1023;
            wt[WF2_OFF + t] = __float2half_rn(wf2[(size_t)k * 512 + n]);
            return;
        }
        t -= 524288;
        if (t < 262144) {
            int n = t >> 9, k = t & 511;
            wt[WS1_OFF + t] = __float2half_rn(ws1[(size_t)k * 512 + n]);
        }
        return;
    }
    int i = (bid - NBX - NBW) * 256 + tid;
    const float4* wq4 = (const float4*)(wq + (size_t)i * 512);
    const float4* wk4 = (const float4*)(wk + (size_t)i * 512);
    const float4* bk4 = (const float4*)bk;
    const float4* bq4 = (const float4*)bq;
    float sa = 0.f, sb = 0.f, so = 0.f;
#pragma unroll 4
    for (int o4 = 0; o4 < 128; o4++) {
        float4 q = wq4[o4], kk = wk4[o4];
        float4 vb = bk4[o4], vq = bq4[o4];
        sa += q.x * vb.x + q.y * vb.y + q.z * vb.z + q.w * vb.w;
        sb += kk.x * vq.x + kk.y * vq.y + kk.z * vq.z + kk.w * vq.w;
    }
    for (int o = 0; o < 512; o++)
        so += bv[o] * wo[(size_t)o * 512 + i];
    w_a[i] = sa;
    buv[i] = sb;
    buv[512 + i] = so + bo[i];
    if (bid == NBX + NBW) {
        float gsum = bq[tid] * bk[tid] + bq[tid + 256] * bk[tid + 256];
        gsum = warp_sum(gsum);
        __shared__ float sm[8];
        if ((tid & 31) == 0) sm[tid >> 5] = gsum;
        __syncthreads();
        if (tid == 0) {
            float g = 0.f;
#pragma unroll
            for (int w = 0; w < 8; w++) g += sm[w];
            gamma[0] = g;
        }
    }
}

// ---------------------------------------------------------------------------
// Fused attention + residual + LN1 (unchanged from R14)
// ---------------------------------------------------------------------------
__global__ __launch_bounds__(256, 4)
void attn_ln_kernel(const float* __restrict__ sp, const __half* __restrict__ xh,
                    const __half* __restrict__ vbuf,
                    const float* __restrict__ w_a,
                    const float* __restrict__ gamma_p,
                    const float* __restrict__ g1, const float* __restrict__ be1,
                    __half* __restrict__ hh)
{
    int gw   = (blockIdx.x * 256 + threadIdx.x) >> 5;
    int lane = threadIdx.x & 31;
    if (gw >= B_) return;

    float pv = sp[(size_t)gw * 32 + lane];
    pv += __shfl_xor_sync(0xffffffffu, pv, 1);
    pv += __shfl_xor_sync(0xffffffffu, pv, 2);
    pv += __shfl_xor_sync(0xffffffffu, pv, 4);
    float s00 = __shfl_sync(0xffffffffu, pv, 0);
    float s01 = __shfl_sync(0xffffffffu, pv, 8);
    float s10 = __shfl_sync(0xffffffffu, pv, 16);
    float s11 = __shfl_sync(0xffffffffu, pv, 24);

    const __half* xb = xh + (size_t)gw * 1024;
    const uint4* x0 = (const uint4*)(xb);
    const uint4* x1 = (const uint4*)(xb + 512);
    const float4* wa4 = (const float4*)w_a;

    uint4 xx0[2], xx1[2];
    float a0s = 0.f, a1s = 0.f;
#pragma unroll
    for (int r = 0; r < 2; r++) {
        int i = lane + 32 * r;
        xx0[r] = x0[i];
        xx1[r] = x1[i];
        float4 wa0 = wa4[2 * i], wa1 = wa4[2 * i + 1];
        a0s += dot8f(xx0[r], wa0, wa1);
        a1s += dot8f(xx1[r], wa0, wa1);
    }
    a0s = warp_sum(a0s);
    a1s = warp_sum(a1s);

    const float gmm = gamma_p[0];
    s00 += a0s + gmm;
    s01 += a0s + gmm;
    s10 += a1s + gmm;
    s11 += a1s + gmm;

    const float inv_scale = 1.0f / 22.627416997969522f;
    s00 *= inv_scale; s01 *= inv_scale; s10 *= inv_scale; s11 *= inv_scale;
    s00 = s00 > 0.f ? s00 : 0.2f * s00;
    s01 = s01 > 0.f ? s01 : 0.2f * s01;
    s10 = s10 > 0.f ? s10 : 0.2f * s10;
    s11 = s11 > 0.f ? s11 : 0.2f * s11;

    float m0 = fmaxf(s00, s01), m1 = fmaxf(s10, s11);
    float e00 = expf(s00 - m0), e01 = expf(s01 - m0);
    float e10 = expf(s10 - m1), e11 = expf(s11 - m1);
    float i0 = 1.0f / (e00 + e01), i1 = 1.0f / (e10 + e11);
    float a00 = e00 * i0, a01 = e01 * i0;
    float a10 = e10 * i1, a11 = e11 * i1;

    const uint4* v0 = (const uint4*)(vbuf + (size_t)gw * 1024);
    const uint4* v1 = v0 + 64;

    uint4 vv0[2], vv1[2];
    float sum0 = 0.f, sq0 = 0.f, sum1 = 0.f, sq1 = 0.f;
#pragma unroll
    for (int r = 0; r < 2; r++) {
        int i = lane + 32 * r;
        vv0[r] = v0[i];
        vv1[r] = v1[i];
        const __half2* p0 = (const __half2*)&vv0[r];
        const __half2* p1 = (const __half2*)&vv1[r];
        const __half2* px0 = (const __half2*)&xx0[r];
        const __half2* px1 = (const __half2*)&xx1[r];
#pragma unroll
        for (int j = 0; j < 4; j++) {
            float2 f0 = __half22float2(p0[j]);
            float2 f1 = __half22float2(p1[j]);
            float2 fx0 = __half22float2(px0[j]);
            float2 fx1 = __half22float2(px1[j]);
            float v0a = fx0.x + a00 * f0.x + a01 * f1.x;
            float v0b = fx0.y + a00 * f0.y + a01 * f1.y;
            float v1a = fx1.x + a10 * f0.x + a11 * f1.x;
            float v1b = fx1.y + a10 * f0.y + a11 * f1.y;
            sum0 += v0a + v0b;  sq0 += v0a * v0a + v0b * v0b;
            sum1 += v1a + v1b;  sq1 += v1a * v1a + v1b * v1b;
        }
    }
    sum0 = warp_sum(sum0); sq0 = warp_sum(sq0);
    sum1 = warp_sum(sum1); sq1 = warp_sum(sq1);
    float mu0 = sum0 * (1.0f / D_);
    float mu1 = sum1 * (1.0f / D_);
    float rs0 = rsqrtf(sq0 * (1.0f / D_) - mu0 * mu0 + 1e-5f);
    float rs1 = rsqrtf(sq1 * (1.0f / D_) - mu1 * mu1 + 1e-5f);

    const float4* g4 = (const float4*)g1;
    const float4* b4 = (const float4*)be1;
    __half* hh0 = hh + (size_t)gw * 1024;

#pragma unroll
    for (int r = 0; r < 2; r++) {
        int i = lane + 32 * r;
        const __half2* p0 = (const __half2*)&vv0[r];
        const __half2* p1 = (const __half2*)&vv1[r];
        const __half2* px0 = (const __half2*)&xx0[r];
        const __half2* px1 = (const __half2*)&xx1[r];
        uint4 o0u, o1u;
        __half2* q0o = (__half2*)&o0u;
        __half2* q1o = (__half2*)&o1u;
#pragma unroll
        for (int j = 0; j < 4; j++) {
            float2 f0 = __half22float2(p0[j]);
            float2 f1 = __half22float2(p1[j]);
            float2 fx0 = __half22float2(px0[j]);
            float2 fx1 = __half22float2(px1[j]);
            float v0a = fx0.x + a00 * f0.x + a01 * f1.x;
            float v0b = fx0.y + a00 * f0.y + a01 * f1.y;
            float v1a = fx1.x + a10 * f0.x + a11 * f1.x;
            float v1b = fx1.y + a10 * f0.y + a11 * f1.y;
            float4 G = g4[2 * i + (j >> 1)];
            float4 Bv = b4[2 * i + (j >> 1)];
            float gx = (j & 1) ? G.z : G.x;
            float gy = (j & 1) ? G.w : G.y;
            float bx = (j & 1) ? Bv.z : Bv.x;
            float by = (j & 1) ? Bv.w : Bv.y;
            q0o[j] = __floats2half2_rn((v0a - mu0) * rs0 * gx + bx,
                                       (v0b - mu0) * rs0 * gy + by);
            q1o[j] = __floats2half2_rn((v1a - mu1) * rs1 * gx + bx,
                                       (v1b - mu1) * rs1 * gy + by);
        }
        ((uint4*)(hh0))[i]       = o0u;
        ((uint4*)(hh0 + 512))[i] = o1u;
    }
}

// ---------------------------------------------------------------------------
// out = LayerNorm(P) * g + be ; P fp16 (pre-summed h+ffn); fp32 out + fp16 copy
// ---------------------------------------------------------------------------
__global__ __launch_bounds__(256)
void ln_kernel(const __half* __restrict__ P,
               const float* __restrict__ g, const float* __restrict__ be,
               float* __restrict__ out, __half* __restrict__ oh)
{
    int row  = (blockIdx.x * 256 + threadIdx.x) >> 5;
    int lane = threadIdx.x & 31;
    if (row >= T_) return;

    const uint4* p4 = (const uint4*)(P + (size_t)row * D_);

    float s[16];
    float sum = 0.f, sq = 0.f;
#pragma unroll
    for (int r = 0; r < 2; r++) {
        int i = lane + 32 * r;
        uint4 pu = p4[i];
        const __half2* pp = (const __half2*)&pu;
#pragma unroll
        for (int j = 0; j < 4; j++) {
            float2 fp = __half22float2(pp[j]);
            s[r*8 + 2*j]     = fp.x;
            s[r*8 + 2*j + 1] = fp.y;
            sum += fp.x + fp.y;
            sq  += fp.x * fp.x + fp.y * fp.y;
        }
    }
    sum = warp_sum(sum);
    sq  = warp_sum(sq);
    float mu  = sum * (1.0f / D_);
    float var = sq * (1.0f / D_) - mu * mu;
    float rs  = rsqrtf(var + 1e-5f);

    const float4* g4 = (const float4*)g;
    const float4* b4 = (const float4*)be;
    float4* o4 = (float4*)(out + (size_t)row * D_);
    __half* oh0 = oh + (size_t)row * D_;

#pragma unroll
    for (int r = 0; r < 2; r++) {
        int i = lane + 32 * r;
        uint4 hu;
        __half2* qh = (__half2*)&hu;
#pragma unroll
        for (int q = 0; q < 2; q++) {
            float4 G = g4[2 * i + q], Bv = b4[2 * i + q];
            float4 o;
            o.x = (s[r*8 + 4*q]     - mu) * rs * G.x + Bv.x;
            o.y = (s[r*8 + 4*q + 1] - mu) * rs * G.y + Bv.y;
            o.z = (s[r*8 + 4*q + 2] - mu) * rs * G.z + Bv.z;
            o.w = (s[r*8 + 4*q + 3] - mu) * rs * G.w + Bv.w;
            o4[2 * i + q] = o;
            qh[2*q]   = __floats2half2_rn(o.x, o.y);
            qh[2*q+1] = __floats2half2_rn(o.z, o.w);
        }
        ((uint4*)oh0)[i] = hu;
    }
}

// ---------------------------------------------------------------------------
// Final stage (unchanged from R14)
// ---------------------------------------------------------------------------
__global__ __launch_bounds__(256)
void final_kernel(const float* __restrict__ sp, const __half* __restrict__ rh,
                  float* __restrict__ fused, float* __restrict__ alpha)
{
    int gw   = (blockIdx.x * 256 + threadIdx.x) >> 5;
    int lane = threadIdx.x & 31;
    if (gw >= B_) return;

    float v = (lane < 16) ? sp[(size_t)gw * 16 + lane] : 0.f;
    v += __shfl_xor_sync(0xffffffffu, v, 1);
    v += __shfl_xor_sync(0xffffffffu, v, 2);
    v += __shfl_xor_sync(0xffffffffu, v, 4);
    float d0 = __shfl_sync(0xffffffffu, v, 0);
    float d1 = __shfl_sync(0xffffffffu, v, 8);

    float m  = fmaxf(d0, d1);
    float e0 = expf(d0 - m), e1 = expf(d1 - m);
    float inv = 1.0f / (e0 + e1);
    float a0 = e0 * inv, a1 = e1 * inv;
    if (lane == 0) {
        alpha[(size_t)gw * 2 + 0] = a0;
        alpha[(size_t)gw * 2 + 1] = a1;
    }

    const uint4* f0 = (const uint4*)(rh + (size_t)gw * 2 * D_);
    const uint4* f1 = f0 + D_ / 8;

    float fr[16];
    float sum = 0.f, sq = 0.f;
#pragma unroll
    for (int r = 0; r < 2; r++) {
        int i = lane + 32 * r;
        uint4 xu0 = f0[i], xu1 = f1[i];
        const __half2* p0 = (const __half2*)&xu0;
        const __half2* p1 = (const __half2*)&xu1;
#pragma unroll
        for (int j = 0; j < 4; j++) {
            float2 v0 = __half22float2(p0[j]);
            float2 v1 = __half22float2(p1[j]);
            float t0 = a0 * v0.x + a1 * v1.x;
            float t1 = a0 * v0.y + a1 * v1.y;
            fr[r*8 + 2*j]     = t0;
            fr[r*8 + 2*j + 1] = t1;
            sum += t0 + t1;
            sq  += t0 * t0 + t1 * t1;
        }
    }
    sum = warp_sum(sum);
    sq  = warp_sum(sq);
    float mu  = sum * (1.0f / D_);
    float var = sq * (1.0f / D_) - mu * mu;
    float rs  = rsqrtf(var + 1e-5f);

    float4* fo = (float4*)(fused + (size_t)gw * D_);
#pragma unroll
    for (int r = 0; r < 2; r++) {
        int i = lane + 32 * r;
#pragma unroll
        for (int q = 0; q < 2; q++) {
            float4 o;
            o.x = (fr[r*8 + 4*q]     - mu) * rs;
            o.y = (fr[r*8 + 4*q + 1] - mu) * rs;
            o.z = (fr[r*8 + 4*q + 2] - mu) * rs;
            o.w = (fr[r*8 + 4*q + 3] - mu) * rs;
            fo[2 * i + q] = o;
        }
    }
}

// ---------------------------------------------------------------------------
// Launch
// ---------------------------------------------------------------------------
extern "C" void kernel_launch(void* const* d_in, const int* in_sizes, int n_in,
                              void* d_out, int out_size)
{
    const float* x   = (const float*)d_in[0];
    const float* wq  = (const float*)d_in[1];
    const float* bq  = (const float*)d_in[2];
    const float* wk  = (const float*)d_in[3];
    const float* bk  = (const float*)d_in[4];
    const float* wv  = (const float*)d_in[5];
    const float* bv  = (const float*)d_in[6];
    const float* wo  = (const float*)d_in[7];
    const float* bo  = (const float*)d_in[8];
    const float* g1  = (const float*)d_in[9];
    const float* be1 = (const float*)d_in[10];
    const float* wf1 = (const float*)d_in[11];
    const float* bf1 = (const float*)d_in[12];
    const float* wf2 = (const float*)d_in[13];
    const float* bf2 = (const float*)d_in[14];
    const float* g2  = (const float*)d_in[15];
    const float* be2 = (const float*)d_in[16];
    const float* ws1 = (const float*)d_in[17];
    const float* bs1 = (const float*)d_in[18];
    const float* ws2 = (const float*)d_in[19];

    float *sp, *buv, *wa, *gma;
    __half *xh, *hh, *rh, *ph, *fh, *wt, *wq16, *wk16, *wv16;
    cudaGetSymbolAddress((void**)&sp, g_sp);
    cudaGetSymbolAddress((void**)&buv, g_buv);
    cudaGetSymbolAddress((void**)&wa, g_wa);
    cudaGetSymbolAddress((void**)&gma, g_gamma);
    cudaGetSymbolAddress((void**)&xh, g_xh);
    cudaGetSymbolAddress((void**)&hh, g_hh);
    cudaGetSymbolAddress((void**)&rh, g_rh);
    cudaGetSymbolAddress((void**)&ph, g_ph);
    cudaGetSymbolAddress((void**)&fh, g_fh);
    cudaGetSymbolAddress((void**)&wt, g_wt);
    cudaGetSymbolAddress((void**)&wq16, g_wq16);
    cudaGetSymbolAddress((void**)&wk16, g_wk16);
    cudaGetSymbolAddress((void**)&wv16, g_wv16);

    cudaFuncSetAttribute(gemm_mma, cudaFuncAttributeMaxDynamicSharedMemorySize,
                         GEMM_SMEM);

    float* out     = (float*)d_out;
    float* fused   = out;
    float* alpha   = out + (size_t)B_ * D_;
    float* refined = alpha + (size_t)B_ * N_;

    dim3 blk(256);

    // one mega-prep launch
    prep_all<<<PREP_BLOCKS, 256>>>(x, wq, wk, wv, wo, wf1, wf2, ws1,
                                   bq, bk, bv, bo,
                                   xh, wq16, wk16, wv16, wt,
                                   wa, gma, buv);

    // Mt (bm 0..3) and Wvo_t (bm 4..7) in ONE launch
    gemm_mma<<<dim3(4, 8), blk, GEMM_SMEM>>>(wk16, wq16, buv, nullptr,
                                             wt + WK_OFF, 512, 512, 3, nullptr,
                                             wt + WO_OFF, wv16, wt + WVO_OFF, 4);

    // fused uv GEMM mode 5: u'-dot partials -> sp[T,16]; v' fp16 -> ph[T,512]
    gemm_mma<<<dim3(8, T_ / 128), blk, GEMM_SMEM>>>(xh, wt + WK_OFF, buv,
                                                    sp, ph, 512, 512, 5, nullptr,
                                                    nullptr, nullptr, nullptr, 1 << 30);
    // fused attention + residual + LN1 -> hh fp16
    attn_ln_kernel<<<B_ / 8, 256>>>(sp, xh, ph, wa, gma, g1, be1, hh);
    // FFN1 (fp16 + ReLU)
    gemm_mma<<<dim3(8, T_ / 128), blk, GEMM_SMEM>>>(hh, wt + WF1_OFF, bf1,
                                                    nullptr, fh, 1024, 512, 2, nullptr,
                                                    nullptr, nullptr, nullptr, 1 << 30);
    // FFN2 mode 6: ph = fp16(ffn_out + hh)   (residual fused in epilogue)
    gemm_mma<<<dim3(4, T_ / 128), blk, GEMM_SMEM>>>(fh, wt + WF2_OFF, bf2,
                                                    nullptr, ph, 512, 1024, 6, nullptr,
                                                    nullptr, nullptr, hh, 1 << 30);
    // pure LN2 (single input stream)
    ln_kernel<<<T_ / 8, 256>>>(ph, g2, be2, refined, rh);
    // score MLP fused: partials = relu(refined@ws1 + bs1) . ws2
    gemm_mma<<<dim3(4, T_ / 128), blk, GEMM_SMEM>>>(rh, wt + WS1_OFF, bs1,
                                                    sp, nullptr, 512, 512, 4, ws2,
                                                    nullptr, nullptr, nullptr, 1 << 30);
    // softmax + pooling + final LN (reads fp16 rh)
    final_kernel<<<B_ / 8, 256>>>(sp, rh, fused, alpha);
}

// round 16
// speedup vs baseline: 1.0419x; 1.0419x over previous
#include <cuda_runtime.h>
#include <cuda_fp16.h>
#include <cstdint>

// ---------------------------------------------------------------------------
// Problem constants
// ---------------------------------------------------------------------------
#define B_   65536
#define N_   2
#define D_   512
#define T_   (B_ * N_)          // 131072 tokens
#define TD_  ((size_t)T_ * D_)  // 67,108,864

// ---------------------------------------------------------------------------
// Scratch (static __device__ arrays)
// ---------------------------------------------------------------------------
__device__ float  g_sp[(size_t)T_ * 16];  // score partials
__device__ float  g_buv[1024];     // bias for uv GEMM: w_b | bvo
__device__ float  g_wa[512], g_gamma[1];

__device__ __half g_xh[TD_];
__device__ __half g_hh[TD_];       // h fp16 (residual + FFN input)
__device__ __half g_rh[TD_];
__device__ __half g_ph[TD_];       // v' buffer, later FFN2 fp16 intermediate
__device__ __half g_fh[2 * TD_];
__device__ __half g_wq16[262144], g_wk16[262144], g_wv16[262144]; // row-major fp16

// transposed fp16 weights, [N,K] layout
#define WK_OFF  262144   // Mt lives here; contiguous with WVO for fused uv GEMM
#define WVO_OFF 524288   // Wvo_t lives here
#define WO_OFF  786432   // wo_t (used only to build Wvo_t)
#define WF1_OFF 1048576
#define WF2_OFF 1572864
#define WS1_OFF 2097152
__device__ __half g_wt[2359296];

// ---------------------------------------------------------------------------
// PTX helpers (baseline sm_80+)
// ---------------------------------------------------------------------------
__device__ __forceinline__ uint32_t smem_u32(const void* smem_ptr) {
    uint32_t addr;
    asm("{ .reg .u64 tmp; cvta.to.shared.u64 tmp, %1; cvt.u32.u64 %0, tmp; }"
        : "=r"(addr) : "l"(smem_ptr));
    return addr;
}

#define CP16(dst, src) \
    asm volatile("cp.async.cg.shared.global [%0], [%1], 16;" \
        :: "r"(dst), "l"(src))

#define CP_COMMIT() asm volatile("cp.async.commit_group;" ::: "memory")
#define CP_WAIT(n)  asm volatile("cp.async.wait_group %0;" :: "n"(n) : "memory")

#define LDSM4(r0, r1, r2, r3, a) \
    asm volatile("ldmatrix.sync.aligned.m8n8.x4.shared.b16 {%0,%1,%2,%3}, [%4];" \
        : "=r"(r0), "=r"(r1), "=r"(r2), "=r"(r3) : "r"(a))

#define MMAH(d, a0, a1, a2, a3, b0, b1) \
    asm volatile("mma.sync.aligned.m16n8k16.row.col.f32.f16.f16.f32 " \
        "{%0,%1,%2,%3}, {%4,%5,%6,%7}, {%8,%9}, {%0,%1,%2,%3};" \
        : "+f"((d)[0]), "+f"((d)[1]), "+f"((d)[2]), "+f"((d)[3]) \
        : "r"(a0), "r"(a1), "r"(a2), "r"(a3), "r"(b0), "r"(b1))

__device__ __forceinline__ float warp_sum(float v) {
#pragma unroll
    for (int o = 16; o; o >>= 1) v += __shfl_xor_sync(0xffffffffu, v, o);
    return v;
}

// dot of 8 fp16 (uint4) with 8 fp32 (two float4)
__device__ __forceinline__ float dot8f(uint4 a, float4 w0, float4 w1) {
    const __half2* pa = (const __half2*)&a;
    float2 f0 = __half22float2(pa[0]);
    float2 f1 = __half22float2(pa[1]);
    float2 f2 = __half22float2(pa[2]);
    float2 f3 = __half22float2(pa[3]);
    return f0.x * w0.x + f0.y * w0.y + f1.x * w0.z + f1.y * w0.w +
           f2.x * w1.x + f2.y * w1.y + f3.x * w1.z + f3.y * w1.w;
}

// ---------------------------------------------------------------------------
// mma.sync GEMM: CTA 128x128, 8 warps, K-chunk 64, 3-stage cp.async,
// 2 CTAs/SM, stride-144B smem rows.
// mode: 0 fp32; 1 fp32+ReLU; 2 fp16+ReLU; 3 fp16;
//       4 score-fused: relu(v+bias) dot ws2 -> partials Cf[row*8 + bn*2 + wn]
//       5 uv-fused: bn<4 -> u'.x_m partials; bn>=4 -> v' fp16 [T,512]
// Dual-problem: if A2 != nullptr and bm >= bsplit -> (A2, B2, C2).
// ---------------------------------------------------------------------------
#define STAGES        3
#define ROW_STRIDE    144
#define MAT_BYTES     18432
#define STAGE_BYTES   36864
#define GEMM_SMEM     (STAGES * STAGE_BYTES)   // 110592

__global__ __launch_bounds__(256, 2)
void gemm_mma(const __half* __restrict__ A, const __half* __restrict__ B,
              const float* __restrict__ bias,
              float* __restrict__ Cf, __half* __restrict__ Ch,
              int N, int K, int mode, const float* __restrict__ ws2,
              const __half* A2, const __half* B2, __half* C2, int bsplit)
{
    extern __shared__ char smem[];
    const uint32_t sb = smem_u32(smem);
    const int tid  = threadIdx.x;
    const int lane = tid & 31;
    const int wid  = tid >> 5;
    const int wm   = wid & 3;
    const int wn   = wid >> 2;
    const int bn   = blockIdx.x;
    int bm         = blockIdx.y;
    const int Kb   = K * 2;

    const __half* Ap = A;
    const __half* Bp = B;
    __half*       Chp = Ch;
    if (A2 != nullptr && bm >= bsplit) {
        bm -= bsplit;
        Ap = A2; Bp = B2; Chp = C2;
    }

    const char* gA = (const char*)(Ap + (size_t)bm * 128 * K);
    const char* gB = (const char*)(Bp + (size_t)bn * 128 * K);

    const int lr  = tid >> 1;
    const int lcb = (tid & 1) * 64;
    const size_t   goff = (size_t)lr * Kb + lcb;
    const uint32_t soff = (uint32_t)lr * ROW_STRIDE + lcb;

    float acc[2][8][4];
#pragma unroll
    for (int mi = 0; mi < 2; mi++)
#pragma unroll
        for (int ni = 0; ni < 8; ni++)
#pragma unroll
            for (int r = 0; r < 4; r++) acc[mi][ni][r] = 0.0f;

    const int nch = K >> 6;

#define LOAD_STAGE(stage, kc) do {                                        \
        uint32_t d = sb + (uint32_t)(stage) * STAGE_BYTES + soff;         \
        size_t   g = goff + (size_t)(kc) * 128;                           \
        CP16(d,                   gA + g);                                \
        CP16(d + 16,              gA + g + 16);                           \
        CP16(d + 32,              gA + g + 32);                           \
        CP16(d + 48,              gA + g + 48);                           \
        CP16(d + MAT_BYTES,       gB + g);                                \
        CP16(d + MAT_BYTES + 16,  gB + g + 16);                           \
        CP16(d + MAT_BYTES + 32,  gB + g + 32);                           \
        CP16(d + MAT_BYTES + 48,  gB + g + 48);                           \
    } while (0)

#pragma unroll
    for (int s = 0; s < STAGES - 1; s++) { LOAD_STAGE(s, s); CP_COMMIT(); }

    const uint32_t a_row  = (uint32_t)(wm * 32 + (lane & 15));
    const uint32_t a_coff = (uint32_t)((lane >> 4) * 16);
    const uint32_t b_row  = (uint32_t)(wn * 64 + ((lane >> 4) * 8) + (lane & 7));
    const uint32_t b_coff = (uint32_t)(((lane >> 3) & 1) * 16);

    int cur = 0;
    int ld  = STAGES - 1;

#pragma unroll 1
    for (int i = 0; i < nch; i++) {
        CP_WAIT(STAGES - 2);
        __syncthreads();

        int nxt = i + STAGES - 1;
        if (nxt < nch) LOAD_STAGE(ld, nxt);
        CP_COMMIT();

        const uint32_t base = sb + (uint32_t)cur * STAGE_BYTES;

#pragma unroll
        for (int kk = 0; kk < 4; kk++) {
            const uint32_t kb = kk * 32;
            uint32_t ar[2][4], br[8][2];
#pragma unroll
            for (int mi = 0; mi < 2; mi++) {
                uint32_t ad = base + (a_row + mi * 16) * ROW_STRIDE + kb + a_coff;
                LDSM4(ar[mi][0], ar[mi][1], ar[mi][2], ar[mi][3], ad);
            }
#pragma unroll
            for (int p = 0; p < 4; p++) {
                uint32_t bd = base + MAT_BYTES +
                              (b_row + p * 16) * ROW_STRIDE + kb + b_coff;
                uint32_t r0, r1, r2, r3;
                LDSM4(r0, r1, r2, r3, bd);
                br[2*p][0] = r0;   br[2*p][1] = r1;
                br[2*p+1][0] = r2; br[2*p+1][1] = r3;
            }
#pragma unroll
            for (int mi = 0; mi < 2; mi++)
#pragma unroll
                for (int ni = 0; ni < 8; ni++)
                    MMAH(acc[mi][ni], ar[mi][0], ar[mi][1], ar[mi][2], ar[mi][3],
                         br[ni][0], br[ni][1]);
        }
        cur = (cur + 1 == STAGES) ? 0 : cur + 1;
        ld  = (ld  + 1 == STAGES) ? 0 : ld  + 1;
    }
#undef LOAD_STAGE

    // epilogue; bias (and ws2) hoisted out of the mi loop
    const int row0 = bm * 128 + wm * 32 + (lane >> 2);
    const int col0 = bn * 128 + wn * 64 + (lane & 3) * 2;

    float bv0[8], bv1[8];
#pragma unroll
    for (int ni = 0; ni < 8; ni++) {
        bv0[ni] = __ldg(bias + col0 + ni * 8);
        bv1[ni] = __ldg(bias + col0 + ni * 8 + 1);
    }

    if (mode == 5 && bn < 4) {
#pragma unroll
        for (int mi = 0; mi < 2; mi++) {
            const int r  = row0 + mi * 16;
            const int r2 = r + 8;
            const __half* xs0 = Ap + (size_t)(r  & ~1) * 512;
            const __half* xs2 = Ap + (size_t)(r2 & ~1) * 512;
            float pa00 = 0.f, pa01 = 0.f, pa10 = 0.f, pa11 = 0.f;
#pragma unroll
            for (int ni = 0; ni < 8; ni++) {
                const int c = col0 + ni * 8;
                float u00 = acc[mi][ni][0] + bv0[ni];
                float u01 = acc[mi][ni][1] + bv1[ni];
                float u10 = acc[mi][ni][2] + bv0[ni];
                float u11 = acc[mi][ni][3] + bv1[ni];
                float2 fa = __half22float2(*(const __half2*)(xs0 + c));
                float2 fb = __half22float2(*(const __half2*)(xs0 + 512 + c));
                float2 fc = __half22float2(*(const __half2*)(xs2 + c));
                float2 fd = __half22float2(*(const __half2*)(xs2 + 512 + c));
                pa00 += u00 * fa.x + u01 * fa.y;
                pa01 += u00 * fb.x + u01 * fb.y;
                pa10 += u10 * fc.x + u11 * fc.y;
                pa11 += u10 * fd.x + u11 * fd.y;
            }
            pa00 += __shfl_xor_sync(0xffffffffu, pa00, 1);
            pa00 += __shfl_xor_sync(0xffffffffu, pa00, 2);
            pa01 += __shfl_xor_sync(0xffffffffu, pa01, 1);
            pa01 += __shfl_xor_sync(0xffffffffu, pa01, 2);
            pa10 += __shfl_xor_sync(0xffffffffu, pa10, 1);
            pa10 += __shfl_xor_sync(0xffffffffu, pa10, 2);
            pa11 += __shfl_xor_sync(0xffffffffu, pa11, 1);
            pa11 += __shfl_xor_sync(0xffffffffu, pa11, 2);
            if ((lane & 3) == 0) {
                Cf[(size_t)r  * 16 + 0 + bn * 2 + wn] = pa00;
                Cf[(size_t)r  * 16 + 8 + bn * 2 + wn] = pa01;
                Cf[(size_t)r2 * 16 + 0 + bn * 2 + wn] = pa10;
                Cf[(size_t)r2 * 16 + 8 + bn * 2 + wn] = pa11;
            }
        }
        return;
    }

    float wv0[8], wv1[8];
    if (mode == 4) {
#pragma unroll
        for (int ni = 0; ni < 8; ni++) {
            wv0[ni] = __ldg(ws2 + col0 + ni * 8);
            wv1[ni] = __ldg(ws2 + col0 + ni * 8 + 1);
        }
    }

#pragma unroll
    for (int mi = 0; mi < 2; mi++) {
        float s0 = 0.f, s1 = 0.f;
#pragma unroll
        for (int ni = 0; ni < 8; ni++) {
            const int r = row0 + mi * 16;
            const int c = col0 + ni * 8;
            float v00 = acc[mi][ni][0] + bv0[ni];
            float v01 = acc[mi][ni][1] + bv1[ni];
            float v10 = acc[mi][ni][2] + bv0[ni];
            float v11 = acc[mi][ni][3] + bv1[ni];
            if (mode == 1 || mode == 2 || mode == 4) {
                v00 = fmaxf(v00, 0.0f); v01 = fmaxf(v01, 0.0f);
                v10 = fmaxf(v10, 0.0f); v11 = fmaxf(v11, 0.0f);
            }
            if (mode == 4) {
                s0 += v00 * wv0[ni] + v01 * wv1[ni];
                s1 += v10 * wv0[ni] + v11 * wv1[ni];
            } else if (mode == 5) {
                __half2 h0 = __floats2half2_rn(v00, v01);
                __half2 h1 = __floats2half2_rn(v10, v11);
                *(__half2*)(Chp + (size_t)r * 512 + (c - 512))       = h0;
                *(__half2*)(Chp + (size_t)(r + 8) * 512 + (c - 512)) = h1;
            } else if (mode >= 2) {
                __half2 h0 = __floats2half2_rn(v00, v01);
                __half2 h1 = __floats2half2_rn(v10, v11);
                *(__half2*)(Chp + (size_t)r * N + c)       = h0;
                *(__half2*)(Chp + (size_t)(r + 8) * N + c) = h1;
            } else {
                *(float2*)(Cf + (size_t)r * N + c)       = make_float2(v00, v01);
                *(float2*)(Cf + (size_t)(r + 8) * N + c) = make_float2(v10, v11);
            }
        }
        if (mode == 4) {
            s0 += __shfl_xor_sync(0xffffffffu, s0, 1);
            s0 += __shfl_xor_sync(0xffffffffu, s0, 2);
            s1 += __shfl_xor_sync(0xffffffffu, s1, 1);
            s1 += __shfl_xor_sync(0xffffffffu, s1, 2);
            if ((lane & 3) == 0) {
                const int r = row0 + mi * 16;
                Cf[(size_t)r * 8 + bn * 2 + wn]       = s0;
                Cf[(size_t)(r + 8) * 8 + bn * 2 + wn] = s1;
            }
        }
    }
}

// ---------------------------------------------------------------------------
// Mega-prep kernel (R14)
// ---------------------------------------------------------------------------
#define NBX 65536
#define NBW 6912
#define NBB 2
#define PREP_BLOCKS (NBX + NBW + NBB)

__global__ __launch_bounds__(256)
void prep_all(const float* __restrict__ x,
              const float* __restrict__ wq, const float* __restrict__ wk,
              const float* __restrict__ wv, const float* __restrict__ wo,
              const float* __restrict__ wf1, const float* __restrict__ wf2,
              const float* __restrict__ ws1,
              const float* __restrict__ bq, const float* __restrict__ bk,
              const float* __restrict__ bv, const float* __restrict__ bo,
              __half* __restrict__ xh,
              __half* __restrict__ wq16, __half* __restrict__ wk16,
              __half* __restrict__ wv16, __half* __restrict__ wt,
              float* __restrict__ w_a,
              float* __restrict__ gamma, float* __restrict__ buv)
{
    int bid = blockIdx.x;
    int tid = threadIdx.x;

    if (bid < NBX) {
        size_t i = (size_t)bid * 256 + tid;
        float4 v = ((const float4*)x)[i];
        __half2 h0 = __floats2half2_rn(v.x, v.y);
        __half2 h1 = __floats2half2_rn(v.z, v.w);
        uint2 o;
        o.x = *(uint32_t*)&h0;
        o.y = *(uint32_t*)&h1;
        ((uint2*)xh)[i] = o;
        return;
    }
    if (bid < NBX + NBW) {
        int idx = (bid - NBX) * 256 + tid;
        if (idx < 196608) {
            int sec = idx >> 16;
            int i4  = idx & 65535;
            const float* src = sec == 0 ? wq : (sec == 1 ? wk : wv);
            __half* dst      = sec == 0 ? wq16 : (sec == 1 ? wk16 : wv16);
            float4 v = ((const float4*)src)[i4];
            __half2 h0 = __floats2half2_rn(v.x, v.y);
            __half2 h1 = __floats2half2_rn(v.z, v.w);
            uint2 o;
            o.x = *(uint32_t*)&h0;
            o.y = *(uint32_t*)&h1;
            ((uint2*)dst)[i4] = o;
            return;
        }
        int t = idx - 196608;
        if (t < 262144) {
            int n = t >> 9, k = t & 511;
            wt[WO_OFF + t] = __float2half_rn(wo[(size_t)k * 512 + n]);
            return;
        }
        t -= 262144;
        if (t < 524288) {
            int n = t >> 9, k = t & 511;
            wt[WF1_OFF + t] = __float2half_rn(wf1[(size_t)k * 1024 + n]);
            return;
        }
        t -= 524288;
        if (t < 524288) {
            int n = t >> 10, k = t & 1023;
            wt[WF2_OFF + t] = __float2half_rn(wf2[(size_t)k * 512 + n]);
            return;
        }
        t -= 524288;
        if (t < 262144) {
            int n = t >> 9, k = t & 511;
            wt[WS1_OFF + t] = __float2half_rn(ws1[(size_t)k * 512 + n]);
        }
        return;
    }
    int i = (bid - NBX - NBW) * 256 + tid;
    const float4* wq4 = (const float4*)(wq + (size_t)i * 512);
    const float4* wk4 = (const float4*)(wk + (size_t)i * 512);
    const float4* bk4 = (const float4*)bk;
    const float4* bq4 = (const float4*)bq;
    float sa = 0.f, sb = 0.f, so = 0.f;
#pragma unroll 4
    for (int o4 = 0; o4 < 128; o4++) {
        float4 q = wq4[o4], kk = wk4[o4];
        float4 vb = bk4[o4], vq = bq4[o4];
        sa += q.x * vb.x + q.y * vb.y + q.z * vb.z + q.w * vb.w;
        sb += kk.x * vq.x + kk.y * vq.y + kk.z * vq.z + kk.w * vq.w;
    }
    for (int o = 0; o < 512; o++)
        so += bv[o] * wo[(size_t)o * 512 + i];
    w_a[i] = sa;
    buv[i] = sb;
    buv[512 + i] = so + bo[i];
    if (bid == NBX + NBW) {
        float gsum = bq[tid] * bk[tid] + bq[tid + 256] * bk[tid + 256];
        gsum = warp_sum(gsum);
        __shared__ float sm[8];
        if ((tid & 31) == 0) sm[tid >> 5] = gsum;
        __syncthreads();
        if (tid == 0) {
            float g = 0.f;
#pragma unroll
            for (int w = 0; w < 8; w++) g += sm[w];
            gamma[0] = g;
        }
    }
}

// ---------------------------------------------------------------------------
// Fused attention + residual + LN1 (R14)
// ---------------------------------------------------------------------------
__global__ __launch_bounds__(256, 4)
void attn_ln_kernel(const float* __restrict__ sp, const __half* __restrict__ xh,
                    const __half* __restrict__ vbuf,
                    const float* __restrict__ w_a,
                    const float* __restrict__ gamma_p,
                    const float* __restrict__ g1, const float* __restrict__ be1,
                    __half* __restrict__ hh)
{
    int gw   = (blockIdx.x * 256 + threadIdx.x) >> 5;
    int lane = threadIdx.x & 31;
    if (gw >= B_) return;

    float pv = sp[(size_t)gw * 32 + lane];
    pv += __shfl_xor_sync(0xffffffffu, pv, 1);
    pv += __shfl_xor_sync(0xffffffffu, pv, 2);
    pv += __shfl_xor_sync(0xffffffffu, pv, 4);
    float s00 = __shfl_sync(0xffffffffu, pv, 0);
    float s01 = __shfl_sync(0xffffffffu, pv, 8);
    float s10 = __shfl_sync(0xffffffffu, pv, 16);
    float s11 = __shfl_sync(0xffffffffu, pv, 24);

    const __half* xb = xh + (size_t)gw * 1024;
    const uint4* x0 = (const uint4*)(xb);
    const uint4* x1 = (const uint4*)(xb + 512);
    const float4* wa4 = (const float4*)w_a;

    uint4 xx0[2], xx1[2];
    float a0s = 0.f, a1s = 0.f;
#pragma unroll
    for (int r = 0; r < 2; r++) {
        int i = lane + 32 * r;
        xx0[r] = x0[i];
        xx1[r] = x1[i];
        float4 wa0 = wa4[2 * i], wa1 = wa4[2 * i + 1];
        a0s += dot8f(xx0[r], wa0, wa1);
        a1s += dot8f(xx1[r], wa0, wa1);
    }
    a0s = warp_sum(a0s);
    a1s = warp_sum(a1s);

    const float gmm = gamma_p[0];
    s00 += a0s + gmm;
    s01 += a0s + gmm;
    s10 += a1s + gmm;
    s11 += a1s + gmm;

    const float inv_scale = 1.0f / 22.627416997969522f;
    s00 *= inv_scale; s01 *= inv_scale; s10 *= inv_scale; s11 *= inv_scale;
    s00 = s00 > 0.f ? s00 : 0.2f * s00;
    s01 = s01 > 0.f ? s01 : 0.2f * s01;
    s10 = s10 > 0.f ? s10 : 0.2f * s10;
    s11 = s11 > 0.f ? s11 : 0.2f * s11;

    float m0 = fmaxf(s00, s01), m1 = fmaxf(s10, s11);
    float e00 = expf(s00 - m0), e01 = expf(s01 - m0);
    float e10 = expf(s10 - m1), e11 = expf(s11 - m1);
    float i0 = 1.0f / (e00 + e01), i1 = 1.0f / (e10 + e11);
    float a00 = e00 * i0, a01 = e01 * i0;
    float a10 = e10 * i1, a11 = e11 * i1;

    const uint4* v0 = (const uint4*)(vbuf + (size_t)gw * 1024);
    const uint4* v1 = v0 + 64;

    uint4 vv0[2], vv1[2];
    float sum0 = 0.f, sq0 = 0.f, sum1 = 0.f, sq1 = 0.f;
#pragma unroll
    for (int r = 0; r < 2; r++) {
        int i = lane + 32 * r;
        vv0[r] = v0[i];
        vv1[r] = v1[i];
        const __half2* p0 = (const __half2*)&vv0[r];
        const __half2* p1 = (const __half2*)&vv1[r];
        const __half2* px0 = (const __half2*)&xx0[r];
        const __half2* px1 = (const __half2*)&xx1[r];
#pragma unroll
        for (int j = 0; j < 4; j++) {
            float2 f0 = __half22float2(p0[j]);
            float2 f1 = __half22float2(p1[j]);
            float2 fx0 = __half22float2(px0[j]);
            float2 fx1 = __half22float2(px1[j]);
            float v0a = fx0.x + a00 * f0.x + a01 * f1.x;
            float v0b = fx0.y + a00 * f0.y + a01 * f1.y;
            float v1a = fx1.x + a10 * f0.x + a11 * f1.x;
            float v1b = fx1.y + a10 * f0.y + a11 * f1.y;
            sum0 += v0a + v0b;  sq0 += v0a * v0a + v0b * v0b;
            sum1 += v1a + v1b;  sq1 += v1a * v1a + v1b * v1b;
        }
    }
    sum0 = warp_sum(sum0); sq0 = warp_sum(sq0);
    sum1 = warp_sum(sum1); sq1 = warp_sum(sq1);
    float mu0 = sum0 * (1.0f / D_);
    float mu1 = sum1 * (1.0f / D_);
    float rs0 = rsqrtf(sq0 * (1.0f / D_) - mu0 * mu0 + 1e-5f);
    float rs1 = rsqrtf(sq1 * (1.0f / D_) - mu1 * mu1 + 1e-5f);

    const float4* g4 = (const float4*)g1;
    const float4* b4 = (const float4*)be1;
    __half* hh0 = hh + (size_t)gw * 1024;

#pragma unroll
    for (int r = 0; r < 2; r++) {
        int i = lane + 32 * r;
        const __half2* p0 = (const __half2*)&vv0[r];
        const __half2* p1 = (const __half2*)&vv1[r];
        const __half2* px0 = (const __half2*)&xx0[r];
        const __half2* px1 = (const __half2*)&xx1[r];
        uint4 o0u, o1u;
        __half2* q0o = (__half2*)&o0u;
        __half2* q1o = (__half2*)&o1u;
#pragma unroll
        for (int j = 0; j < 4; j++) {
            float2 f0 = __half22float2(p0[j]);
            float2 f1 = __half22float2(p1[j]);
            float2 fx0 = __half22float2(px0[j]);
            float2 fx1 = __half22float2(px1[j]);
            float v0a = fx0.x + a00 * f0.x + a01 * f1.x;
            float v0b = fx0.y + a00 * f0.y + a01 * f1.y;
            float v1a = fx1.x + a10 * f0.x + a11 * f1.x;
            float v1b = fx1.y + a10 * f0.y + a11 * f1.y;
            float4 G = g4[2 * i + (j >> 1)];
            float4 Bv = b4[2 * i + (j >> 1)];
            float gx = (j & 1) ? G.z : G.x;
            float gy = (j & 1) ? G.w : G.y;
            float bx = (j & 1) ? Bv.z : Bv.x;
            float by = (j & 1) ? Bv.w : Bv.y;
            q0o[j] = __floats2half2_rn((v0a - mu0) * rs0 * gx + bx,
                                       (v0b - mu0) * rs0 * gy + by);
            q1o[j] = __floats2half2_rn((v1a - mu1) * rs1 * gx + bx,
                                       (v1b - mu1) * rs1 * gy + by);
        }
        ((uint4*)(hh0))[i]       = o0u;
        ((uint4*)(hh0 + 512))[i] = o1u;
    }
}

// ---------------------------------------------------------------------------
// out = LayerNorm(A + P) * g + be ; A,P fp16; fp32 out + fp16 copy. (R14)
// ---------------------------------------------------------------------------
__global__ __launch_bounds__(256)
void add_ln_kernel(const __half* __restrict__ A, const __half* __restrict__ P,
                   const float* __restrict__ g, const float* __restrict__ be,
                   float* __restrict__ out, __half* __restrict__ oh)
{
    int row  = (blockIdx.x * 256 + threadIdx.x) >> 5;
    int lane = threadIdx.x & 31;
    if (row >= T_) return;

    const uint4* a4 = (const uint4*)(A + (size_t)row * D_);
    const uint4* p4 = (const uint4*)(P + (size_t)row * D_);

    float s[16];
    float sum = 0.f, sq = 0.f;
#pragma unroll
    for (int r = 0; r < 2; r++) {
        int i = lane + 32 * r;
        uint4 au = a4[i], pu = p4[i];
        const __half2* pa = (const __half2*)&au;
        const __half2* pp = (const __half2*)&pu;
#pragma unroll
        for (int j = 0; j < 4; j++) {
            float2 fa = __half22float2(pa[j]);
            float2 fp = __half22float2(pp[j]);
            float v0 = fa.x + fp.x;
            float v1 = fa.y + fp.y;
            s[r*8 + 2*j]     = v0;
            s[r*8 + 2*j + 1] = v1;
            sum += v0 + v1;
            sq  += v0 * v0 + v1 * v1;
        }
    }
    sum = warp_sum(sum);
    sq  = warp_sum(sq);
    float mu  = sum * (1.0f / D_);
    float var = sq * (1.0f / D_) - mu * mu;
    float rs  = rsqrtf(var + 1e-5f);

    const float4* g4 = (const float4*)g;
    const float4* b4 = (const float4*)be;
    float4* o4 = (float4*)(out + (size_t)row * D_);
    __half* oh0 = oh + (size_t)row * D_;

#pragma unroll
    for (int r = 0; r < 2; r++) {
        int i = lane + 32 * r;
        uint4 hu;
        __half2* qh = (__half2*)&hu;
#pragma unroll
        for (int q = 0; q < 2; q++) {
            float4 G = g4[2 * i + q], Bv = b4[2 * i + q];
            float4 o;
            o.x = (s[r*8 + 4*q]     - mu) * rs * G.x + Bv.x;
            o.y = (s[r*8 + 4*q + 1] - mu) * rs * G.y + Bv.y;
            o.z = (s[r*8 + 4*q + 2] - mu) * rs * G.z + Bv.z;
            o.w = (s[r*8 + 4*q + 3] - mu) * rs * G.w + Bv.w;
            o4[2 * i + q] = o;
            qh[2*q]   = __floats2half2_rn(o.x, o.y);
            qh[2*q+1] = __floats2half2_rn(o.z, o.w);
        }
        ((uint4*)oh0)[i] = hu;
    }
}

// ---------------------------------------------------------------------------
// Final stage (R14)
// ---------------------------------------------------------------------------
__global__ __launch_bounds__(256)
void final_kernel(const float* __restrict__ sp, const __half* __restrict__ rh,
                  float* __restrict__ fused, float* __restrict__ alpha)
{
    int gw   = (blockIdx.x * 256 + threadIdx.x) >> 5;
    int lane = threadIdx.x & 31;
    if (gw >= B_) return;

    float v = (lane < 16) ? sp[(size_t)gw * 16 + lane] : 0.f;
    v += __shfl_xor_sync(0xffffffffu, v, 1);
    v += __shfl_xor_sync(0xffffffffu, v, 2);
    v += __shfl_xor_sync(0xffffffffu, v, 4);
    float d0 = __shfl_sync(0xffffffffu, v, 0);
    float d1 = __shfl_sync(0xffffffffu, v, 8);

    float m  = fmaxf(d0, d1);
    float e0 = expf(d0 - m), e1 = expf(d1 - m);
    float inv = 1.0f / (e0 + e1);
    float a0 = e0 * inv, a1 = e1 * inv;
    if (lane == 0) {
        alpha[(size_t)gw * 2 + 0] = a0;
        alpha[(size_t)gw * 2 + 1] = a1;
    }

    const uint4* f0 = (const uint4*)(rh + (size_t)gw * 2 * D_);
    const uint4* f1 = f0 + D_ / 8;

    float fr[16];
    float sum = 0.f, sq = 0.f;
#pragma unroll
    for (int r = 0; r < 2; r++) {
        int i = lane + 32 * r;
        uint4 xu0 = f0[i], xu1 = f1[i];
        const __half2* p0 = (const __half2*)&xu0;
        const __half2* p1 = (const __half2*)&xu1;
#pragma unroll
        for (int j = 0; j < 4; j++) {
            float2 v0 = __half22float2(p0[j]);
            float2 v1 = __half22float2(p1[j]);
            float t0 = a0 * v0.x + a1 * v1.x;
            float t1 = a0 * v0.y + a1 * v1.y;
            fr[r*8 + 2*j]     = t0;
            fr[r*8 + 2*j + 1] = t1;
            sum += t0 + t1;
            sq  += t0 * t0 + t1 * t1;
        }
    }
    sum = warp_sum(sum);
    sq  = warp_sum(sq);
    float mu  = sum * (1.0f / D_);
    float var = sq * (1.0f / D_) - mu * mu;
    float rs  = rsqrtf(var + 1e-5f);

    float4* fo = (float4*)(fused + (size_t)gw * D_);
#pragma unroll
    for (int r = 0; r < 2; r++) {
        int i = lane + 32 * r;
#pragma unroll
        for (int q = 0; q < 2; q++) {
            float4 o;
            o.x = (fr[r*8 + 4*q]     - mu) * rs;
            o.y = (fr[r*8 + 4*q + 1] - mu) * rs;
            o.z = (fr[r*8 + 4*q + 2] - mu) * rs;
            o.w = (fr[r*8 + 4*q + 3] - mu) * rs;
            fo[2 * i + q] = o;
        }
    }
}

// ---------------------------------------------------------------------------
// Launch (R14 schedule)
// ---------------------------------------------------------------------------
extern "C" void kernel_launch(void* const* d_in, const int* in_sizes, int n_in,
                              void* d_out, int out_size)
{
    const float* x   = (const float*)d_in[0];
    const float* wq  = (const float*)d_in[1];
    const float* bq  = (const float*)d_in[2];
    const float* wk  = (const float*)d_in[3];
    const float* bk  = (const float*)d_in[4];
    const float* wv  = (const float*)d_in[5];
    const float* bv  = (const float*)d_in[6];
    const float* wo  = (const float*)d_in[7];
    const float* bo  = (const float*)d_in[8];
    const float* g1  = (const float*)d_in[9];
    const float* be1 = (const float*)d_in[10];
    const float* wf1 = (const float*)d_in[11];
    const float* bf1 = (const float*)d_in[12];
    const float* wf2 = (const float*)d_in[13];
    const float* bf2 = (const float*)d_in[14];
    const float* g2  = (const float*)d_in[15];
    const float* be2 = (const float*)d_in[16];
    const float* ws1 = (const float*)d_in[17];
    const float* bs1 = (const float*)d_in[18];
    const float* ws2 = (const float*)d_in[19];

    float *sp, *buv, *wa, *gma;
    __half *xh, *hh, *rh, *ph, *fh, *wt, *wq16, *wk16, *wv16;
    cudaGetSymbolAddress((void**)&sp, g_sp);
    cudaGetSymbolAddress((void**)&buv, g_buv);
    cudaGetSymbolAddress((void**)&wa, g_wa);
    cudaGetSymbolAddress((void**)&gma, g_gamma);
    cudaGetSymbolAddress((void**)&xh, g_xh);
    cudaGetSymbolAddress((void**)&hh, g_hh);
    cudaGetSymbolAddress((void**)&rh, g_rh);
    cudaGetSymbolAddress((void**)&ph, g_ph);
    cudaGetSymbolAddress((void**)&fh, g_fh);
    cudaGetSymbolAddress((void**)&wt, g_wt);
    cudaGetSymbolAddress((void**)&wq16, g_wq16);
    cudaGetSymbolAddress((void**)&wk16, g_wk16);
    cudaGetSymbolAddress((void**)&wv16, g_wv16);

    cudaFuncSetAttribute(gemm_mma, cudaFuncAttributeMaxDynamicSharedMemorySize,
                         GEMM_SMEM);

    float* out     = (float*)d_out;
    float* fused   = out;
    float* alpha   = out + (size_t)B_ * D_;
    float* refined = alpha + (size_t)B_ * N_;

    dim3 blk(256);

    // one mega-prep launch
    prep_all<<<PREP_BLOCKS, 256>>>(x, wq, wk, wv, wo, wf1, wf2, ws1,
                                   bq, bk, bv, bo,
                                   xh, wq16, wk16, wv16, wt,
                                   wa, gma, buv);

    // Mt (bm 0..3) and Wvo_t (bm 4..7) in ONE launch
    gemm_mma<<<dim3(4, 8), blk, GEMM_SMEM>>>(wk16, wq16, buv, nullptr,
                                             wt + WK_OFF, 512, 512, 3, nullptr,
                                             wt + WO_OFF, wv16, wt + WVO_OFF, 4);

    // fused uv GEMM mode 5: u'-dot partials -> sp[T,16]; v' fp16 -> ph[T,512]
    gemm_mma<<<dim3(8, T_ / 128), blk, GEMM_SMEM>>>(xh, wt + WK_OFF, buv,
                                                    sp, ph, 512, 512, 5, nullptr,
                                                    nullptr, nullptr, nullptr, 1 << 30);
    // fused attention + residual + LN1 -> hh fp16
    attn_ln_kernel<<<B_ / 8, 256>>>(sp, xh, ph, wa, gma, g1, be1, hh);
    // FFN
    gemm_mma<<<dim3(8, T_ / 128), blk, GEMM_SMEM>>>(hh, wt + WF1_OFF, bf1,
                                                    nullptr, fh, 1024, 512, 2, nullptr,
                                                    nullptr, nullptr, nullptr, 1 << 30);
    gemm_mma<<<dim3(4, T_ / 128), blk, GEMM_SMEM>>>(fh, wt + WF2_OFF, bf2,
                                                    nullptr, ph, 512, 1024, 3, nullptr,
                                                    nullptr, nullptr, nullptr, 1 << 30);
    add_ln_kernel<<<T_ / 8, 256>>>(hh, ph, g2, be2, refined, rh);
    // score MLP fused: partials = relu(refined@ws1 + bs1) . ws2
    gemm_mma<<<dim3(4, T_ / 128), blk, GEMM_SMEM>>>(rh, wt + WS1_OFF, bs1,
                                                    sp, nullptr, 512, 512, 4, ws2,
                                                    nullptr, nullptr, nullptr, 1 << 30);
    // softmax + pooling + final LN (reads fp16 rh)
    final_kernel<<<B_ / 8, 256>>>(sp, rh, fused, alpha);
}